// round 3
// baseline (speedup 1.0000x reference)
#include <cuda_runtime.h>
#include <cuda_bf16.h>
#include <cstdint>

#define N 8192
#define D 128
#define BM 64
#define BN 64
#define NTILES (N / BN)      // 128
#define NSPLIT 37            // 128 rowblocks * 37 = 4736 = 148 * 32 (exact waves at occ 2)
#define EPS2 0.25f
#define LOG2E 1.4426950408889634f

// ---------------- device scratch (no allocations allowed) ----------------
__device__ float  g_hn[N * D];        // normalized h
__device__ float4 g_pos4[N];          // (x, y, z, x^2+y^2+z^2)
__device__ float  g_se[NSPLIT * N];   // partial sum exp(logit-10)
__device__ float  g_sp[NSPLIT * N];   // partial sum of positive logits
__device__ float  g_cnt[NSPLIT * N];  // partial positive counts

// packed fp32x2 FMA: 2 FMAs per instruction (full-rate path on sm_103a)
#define FMA2(c, a, b) asm("fma.rn.f32x2 %0, %1, %2, %0;" : "+l"(c) : "l"(a), "l"(b))
#define CP16(dst, src) \
    asm volatile("cp.async.cg.shared.global [%0], [%1], 16;\n" :: "r"(dst), "l"(src) : "memory")

// ---------------- prep: L2-normalize rows of h ----------------
__global__ void normalize_kernel(const float* __restrict__ h) {
    int row  = blockIdx.x * 8 + (threadIdx.x >> 5);
    int lane = threadIdx.x & 31;
    const float4* hv = (const float4*)h;
    float4 v = hv[row * 32 + lane];              // 32 float4 per row (D=128)
    float ss = v.x * v.x + v.y * v.y + v.z * v.z + v.w * v.w;
    #pragma unroll
    for (int o = 16; o; o >>= 1) ss += __shfl_xor_sync(0xffffffffu, ss, o);
    float inv = 1.0f / fmaxf(sqrtf(ss), 1e-12f);
    ((float4*)g_hn)[row * 32 + lane] = make_float4(v.x * inv, v.y * inv, v.z * inv, v.w * inv);
}

// ---------------- prep: pack positions + squared norms ----------------
__global__ void pos_kernel(const float* __restrict__ pos) {
    int i = blockIdx.x * blockDim.x + threadIdx.x;
    if (i < N) {
        float x = pos[3 * i], y = pos[3 * i + 1], z = pos[3 * i + 2];
        g_pos4[i] = make_float4(x, y, z, x * x + y * y + z * z);
    }
}

// ---------------- main: streaming sim-GEMM + per-row reductions ----------------
// smem layout (dynamic, 102912 B): As4 [32][65] f4 | Bs4 [2][32][65] f4 | posA[64] | posB[2][64]
#define AS_F4   (32 * 65)          // 2080 float4 = 33280 B
#define BS_OFF  33280
#define PA_OFF  (33280 + 66560)
#define PB_OFF  (PA_OFF + 1024)
#define SMEM_MAIN (PB_OFF + 2048)  // 102912

__global__ void __launch_bounds__(256, 2) main_kernel() {
    extern __shared__ char smem[];
    float4* As4  = (float4*)smem;
    float4* Bs4  = (float4*)(smem + BS_OFF);
    float4* posA = (float4*)(smem + PA_OFF);
    float4* posB = (float4*)(smem + PB_OFF);

    const int tid = threadIdx.x;
    const int tx  = tid & 15;          // 16 column lanes  -> 64 cols (4 each)
    const int ty  = tid >> 4;          // 16 row groups    -> 64 rows (4 each)
    const int rowBase = blockIdx.x * BM;
    const int split   = blockIdx.y;
    const int t0 = (split * NTILES) / NSPLIT;
    const int t1 = ((split + 1) * NTILES) / NSPLIT;
    const int tiles = t1 - t0;

    // tile loader mapping: 64 rows x 4 k-segments of 32 floats
    const int arow = tid & 63, aseg = tid >> 6;

    const uint32_t s_as = (uint32_t)__cvta_generic_to_shared(As4);
    const uint32_t s_bs = (uint32_t)__cvta_generic_to_shared(Bs4);
    const uint32_t s_pa = (uint32_t)__cvta_generic_to_shared(posA);
    const uint32_t s_pb = (uint32_t)__cvta_generic_to_shared(posB);

    // ---- prologue group: A tile + posA + B tile(t0) + posB(t0) ----
    {
        const float* asrc = g_hn + (rowBase + arow) * D + aseg * 32;
        #pragma unroll
        for (int i = 0; i < 8; i++)
            CP16(s_as + (uint32_t)(((aseg * 8 + i) * 65 + arow) * 16), asrc + i * 4);
        if (tid < 64) CP16(s_pa + (uint32_t)(tid * 16), (const float*)&g_pos4[rowBase + tid]);

        const float* bsrc = g_hn + (t0 * BN + arow) * D + aseg * 32;
        #pragma unroll
        for (int i = 0; i < 8; i++)
            CP16(s_bs + (uint32_t)(((aseg * 8 + i) * 65 + arow) * 16), bsrc + i * 4);
        if (tid < 64) CP16(s_pb + (uint32_t)(tid * 16), (const float*)&g_pos4[t0 * BN + tid]);
        asm volatile("cp.async.commit_group;\n" ::: "memory");
    }

    unsigned long long acc[4][4];
    float se[4], sp[4], cnt[4];
    #pragma unroll
    for (int m = 0; m < 4; m++) { se[m] = 0.f; sp[m] = 0.f; cnt[m] = 0.f; }
    #pragma unroll
    for (int m = 0; m < 4; m++)
        #pragma unroll
        for (int n = 0; n < 4; n++) acc[m][n] = 0ull;

    for (int tt = 0; tt < tiles; tt++) {
        const int cur = tt & 1;

        if (tt + 1 < tiles) {
            const int jb = (t0 + tt + 1) * BN;
            const float* bsrc = g_hn + (jb + arow) * D + aseg * 32;
            const uint32_t bbase = s_bs + (uint32_t)((cur ^ 1) * 33280);
            #pragma unroll
            for (int i = 0; i < 8; i++)
                CP16(bbase + (uint32_t)(((aseg * 8 + i) * 65 + arow) * 16), bsrc + i * 4);
            if (tid < 64)
                CP16(s_pb + (uint32_t)(((cur ^ 1) * 64 + tid) * 16), (const float*)&g_pos4[jb + tid]);
            asm volatile("cp.async.commit_group;\n" ::: "memory");
            asm volatile("cp.async.wait_group 1;\n" ::: "memory");
        } else {
            asm volatile("cp.async.wait_group 0;\n" ::: "memory");
        }
        __syncthreads();

        // ---- inner GEMM: 32 k4-steps, 4x4 outputs, packed f32x2 accumulate ----
        const float4* Bc = Bs4 + cur * AS_F4;
        #pragma unroll 8
        for (int k4 = 0; k4 < 32; k4++) {
            ulonglong2 av[4], bv[4];
            #pragma unroll
            for (int m = 0; m < 4; m++)
                av[m] = *(const ulonglong2*)(As4 + k4 * 65 + ty * 4 + m);
            #pragma unroll
            for (int n = 0; n < 4; n++)
                bv[n] = *(const ulonglong2*)(Bc + k4 * 65 + tx * 4 + n);
            #pragma unroll
            for (int m = 0; m < 4; m++)
                #pragma unroll
                for (int n = 0; n < 4; n++) {
                    FMA2(acc[m][n], av[m].x, bv[n].x);
                    FMA2(acc[m][n], av[m].y, bv[n].y);
                }
        }

        // ---- epilogue: fold 16 similarities into row accumulators ----
        const int jBase = (t0 + tt) * BN;
        #pragma unroll
        for (int m = 0; m < 4; m++) {
            float4 pa = posA[ty * 4 + m];
            int gi = rowBase + ty * 4 + m;
            #pragma unroll
            for (int n = 0; n < 4; n++) {
                float4 pb = posB[cur * 64 + tx * 4 + n];
                int gj = jBase + tx * 4 + n;
                float lo, hi;
                asm("mov.b64 {%0,%1}, %2;" : "=f"(lo), "=f"(hi) : "l"(acc[m][n]));
                acc[m][n] = 0ull;
                float sim   = lo + hi;
                float logit = sim * 10.0f;
                // exp(logit - 10) via ex2 (max logit = 10 -> fixed shift, no online max)
                float e;
                float arg = fmaf(logit, LOG2E, -10.0f * LOG2E);
                asm("ex2.approx.ftz.f32 %0, %1;" : "=f"(e) : "f"(arg));
                bool self = (gi == gj);
                float dot3 = pa.x * pb.x + pa.y * pb.y + pa.z * pb.z;
                float d2   = pa.w + pb.w - 2.0f * dot3;
                bool ispos = (d2 < EPS2) && !self;
                se[m]  += self  ? 0.0f : e;
                sp[m]  += ispos ? logit : 0.0f;
                cnt[m] += ispos ? 1.0f : 0.0f;
            }
        }
        __syncthreads();
    }

    // ---- reduce across the 16 column lanes sharing each row ----
    #pragma unroll
    for (int m = 0; m < 4; m++) {
        float a = se[m], b = sp[m], c = cnt[m];
        #pragma unroll
        for (int o = 8; o; o >>= 1) {
            a += __shfl_down_sync(0xffffffffu, a, o, 16);
            b += __shfl_down_sync(0xffffffffu, b, o, 16);
            c += __shfl_down_sync(0xffffffffu, c, o, 16);
        }
        if (tx == 0) {
            int gi = rowBase + ty * 4 + m;
            g_se[split * N + gi]  = a;
            g_sp[split * N + gi]  = b;
            g_cnt[split * N + gi] = c;
        }
    }
}

// ---------------- final: combine splits, per-anchor loss, mean ----------------
__global__ void final_kernel(float* __restrict__ out) {
    __shared__ float sL[256], sV[256];
    int tid = threadIdx.x;
    float sumL = 0.f, sumV = 0.f;
    for (int r = tid; r < N; r += 256) {
        float se = 0.f, sp = 0.f, c = 0.f;
        for (int s = 0; s < NSPLIT; s++) {
            se += g_se[s * N + r];
            sp += g_sp[s * N + r];
            c  += g_cnt[s * N + r];
        }
        float lse = logf(se) + 10.0f;            // undo the fixed shift
        if (c > 0.0f) {
            sumL += -(sp - c * lse) / c;
            sumV += 1.0f;
        }
    }
    sL[tid] = sumL; sV[tid] = sumV;
    __syncthreads();
    for (int o = 128; o; o >>= 1) {
        if (tid < o) { sL[tid] += sL[tid + o]; sV[tid] += sV[tid + o]; }
        __syncthreads();
    }
    if (tid == 0) out[0] = sL[0] / fmaxf(sV[0], 1.0f);
}

// ---------------- launch ----------------
extern "C" void kernel_launch(void* const* d_in, const int* in_sizes, int n_in,
                              void* d_out, int out_size) {
    const float* h   = (const float*)d_in[0];
    const float* pos = (const float*)d_in[1];
    if (n_in >= 2 && in_sizes[0] < in_sizes[1]) {  // defensive: h is the big one
        const float* t = h; h = pos; pos = t;
    }
    float* out = (float*)d_out;

    normalize_kernel<<<N / 8, 256>>>(h);
    pos_kernel<<<N / 256, 256>>>(pos);

    cudaFuncSetAttribute(main_kernel, cudaFuncAttributeMaxDynamicSharedMemorySize, SMEM_MAIN);
    dim3 grid(N / BM, NSPLIT);
    main_kernel<<<grid, 256, SMEM_MAIN>>>();

    final_kernel<<<1, 256>>>(out);
}

// round 4
// speedup vs baseline: 2.3679x; 2.3679x over previous
#include <cuda_runtime.h>
#include <cuda_bf16.h>
#include <cstdint>

#define N 8192
#define D 128
#define BM 64
#define BN 64
#define NTILES (N / BN)      // 128
#define NSPLIT 37            // 128 rowblocks * 37 = 4736 = 148 * 32 (exact waves at occ 2)
#define EPS2 0.25f
#define LOG2E 1.4426950408889634f

// ---------------- device scratch (no allocations allowed) ----------------
__device__ float  g_hn[N * D];        // normalized h
__device__ float4 g_pos4[N];          // (x, y, z, x^2+y^2+z^2)
__device__ float  g_se[NSPLIT * N];   // partial sum exp(logit-10)
__device__ float  g_sp[NSPLIT * N];   // partial sum of positive logits
__device__ float  g_cnt[NSPLIT * N];  // partial positive counts
__device__ float  g_partL[32];        // per-block partial loss sums
__device__ float  g_partV[32];        // per-block partial valid counts

// packed fp32x2 FMA: 2 FMAs per instruction (full-rate path on sm_103a)
#define FMA2(c, a, b) asm("fma.rn.f32x2 %0, %1, %2, %0;" : "+l"(c) : "l"(a), "l"(b))
#define CP16(dst, src) \
    asm volatile("cp.async.cg.shared.global [%0], [%1], 16;\n" :: "r"(dst), "l"(src) : "memory")

// ---------------- prep: L2-normalize rows of h ----------------
__global__ void normalize_kernel(const float* __restrict__ h) {
    int row  = blockIdx.x * 8 + (threadIdx.x >> 5);
    int lane = threadIdx.x & 31;
    const float4* hv = (const float4*)h;
    float4 v = hv[row * 32 + lane];              // 32 float4 per row (D=128)
    float ss = v.x * v.x + v.y * v.y + v.z * v.z + v.w * v.w;
    #pragma unroll
    for (int o = 16; o; o >>= 1) ss += __shfl_xor_sync(0xffffffffu, ss, o);
    float inv = 1.0f / fmaxf(sqrtf(ss), 1e-12f);
    ((float4*)g_hn)[row * 32 + lane] = make_float4(v.x * inv, v.y * inv, v.z * inv, v.w * inv);
}

// ---------------- prep: pack positions + squared norms ----------------
__global__ void pos_kernel(const float* __restrict__ pos) {
    int i = blockIdx.x * blockDim.x + threadIdx.x;
    if (i < N) {
        float x = pos[3 * i], y = pos[3 * i + 1], z = pos[3 * i + 2];
        g_pos4[i] = make_float4(x, y, z, x * x + y * y + z * z);
    }
}

// ---------------- main: streaming sim-GEMM + per-row reductions ----------------
// smem layout (dynamic, 102912 B): As4 [32][65] f4 | Bs4 [2][32][65] f4 | posA[64] | posB[2][64]
#define AS_F4   (32 * 65)          // 2080 float4 = 33280 B
#define BS_OFF  33280
#define PA_OFF  (33280 + 66560)
#define PB_OFF  (PA_OFF + 1024)
#define SMEM_MAIN (PB_OFF + 2048)  // 102912

__global__ void __launch_bounds__(256, 2) main_kernel() {
    extern __shared__ char smem[];
    float4* As4  = (float4*)smem;
    float4* Bs4  = (float4*)(smem + BS_OFF);
    float4* posA = (float4*)(smem + PA_OFF);
    float4* posB = (float4*)(smem + PB_OFF);

    const int tid = threadIdx.x;
    const int tx  = tid & 15;          // column lane: handles cols {tx, tx+16, tx+32, tx+48}
    const int ty  = tid >> 4;          // row group:   handles rows {ty, ty+16, ty+32, ty+48}
    const int rowBase = blockIdx.x * BM;
    const int split   = blockIdx.y;
    const int t0 = (split * NTILES) / NSPLIT;
    const int t1 = ((split + 1) * NTILES) / NSPLIT;
    const int tiles = t1 - t0;

    // tile loader mapping: 64 rows x 4 k-segments of 32 floats
    const int arow = tid & 63, aseg = tid >> 6;

    const uint32_t s_as = (uint32_t)__cvta_generic_to_shared(As4);
    const uint32_t s_bs = (uint32_t)__cvta_generic_to_shared(Bs4);
    const uint32_t s_pa = (uint32_t)__cvta_generic_to_shared(posA);
    const uint32_t s_pb = (uint32_t)__cvta_generic_to_shared(posB);

    // ---- prologue group: A tile + posA + B tile(t0) + posB(t0) ----
    {
        const float* asrc = g_hn + (rowBase + arow) * D + aseg * 32;
        #pragma unroll
        for (int i = 0; i < 8; i++)
            CP16(s_as + (uint32_t)(((aseg * 8 + i) * 65 + arow) * 16), asrc + i * 4);
        if (tid < 64) CP16(s_pa + (uint32_t)(tid * 16), (const float*)&g_pos4[rowBase + tid]);

        const float* bsrc = g_hn + (t0 * BN + arow) * D + aseg * 32;
        #pragma unroll
        for (int i = 0; i < 8; i++)
            CP16(s_bs + (uint32_t)(((aseg * 8 + i) * 65 + arow) * 16), bsrc + i * 4);
        if (tid < 64) CP16(s_pb + (uint32_t)(tid * 16), (const float*)&g_pos4[t0 * BN + tid]);
        asm volatile("cp.async.commit_group;\n" ::: "memory");
    }

    unsigned long long acc[4][4];
    float se[4], sp[4], cnt[4];
    #pragma unroll
    for (int m = 0; m < 4; m++) { se[m] = 0.f; sp[m] = 0.f; cnt[m] = 0.f; }
    #pragma unroll
    for (int m = 0; m < 4; m++)
        #pragma unroll
        for (int n = 0; n < 4; n++) acc[m][n] = 0ull;

    for (int tt = 0; tt < tiles; tt++) {
        const int cur = tt & 1;

        if (tt + 1 < tiles) {
            const int jb = (t0 + tt + 1) * BN;
            const float* bsrc = g_hn + (jb + arow) * D + aseg * 32;
            const uint32_t bbase = s_bs + (uint32_t)((cur ^ 1) * 33280);
            #pragma unroll
            for (int i = 0; i < 8; i++)
                CP16(bbase + (uint32_t)(((aseg * 8 + i) * 65 + arow) * 16), bsrc + i * 4);
            if (tid < 64)
                CP16(s_pb + (uint32_t)(((cur ^ 1) * 64 + tid) * 16), (const float*)&g_pos4[jb + tid]);
            asm volatile("cp.async.commit_group;\n" ::: "memory");
            asm volatile("cp.async.wait_group 1;\n" ::: "memory");
        } else {
            asm volatile("cp.async.wait_group 0;\n" ::: "memory");
        }
        __syncthreads();

        // ---- inner GEMM: 32 k4-steps, 4x4 outputs, packed f32x2 accumulate ----
        // Fragment maps: A row  m*16+ty  -> half-warp broadcast (free)
        //                B col  n*16+tx  -> 16 lanes x 16B contiguous (conflict-free)
        const float4* Bc = Bs4 + cur * AS_F4;
        #pragma unroll 8
        for (int k4 = 0; k4 < 32; k4++) {
            ulonglong2 av[4], bv[4];
            #pragma unroll
            for (int m = 0; m < 4; m++)
                av[m] = *(const ulonglong2*)(As4 + k4 * 65 + m * 16 + ty);
            #pragma unroll
            for (int n = 0; n < 4; n++)
                bv[n] = *(const ulonglong2*)(Bc + k4 * 65 + n * 16 + tx);
            #pragma unroll
            for (int m = 0; m < 4; m++)
                #pragma unroll
                for (int n = 0; n < 4; n++) {
                    FMA2(acc[m][n], av[m].x, bv[n].x);
                    FMA2(acc[m][n], av[m].y, bv[n].y);
                }
        }

        // ---- epilogue: fold 16 similarities into row accumulators ----
        const int jBase = (t0 + tt) * BN;
        #pragma unroll
        for (int m = 0; m < 4; m++) {
            float4 pa = posA[m * 16 + ty];
            int gi = rowBase + m * 16 + ty;
            #pragma unroll
            for (int n = 0; n < 4; n++) {
                float4 pb = posB[cur * 64 + n * 16 + tx];
                int gj = jBase + n * 16 + tx;
                float lo, hi;
                asm("mov.b64 {%0,%1}, %2;" : "=f"(lo), "=f"(hi) : "l"(acc[m][n]));
                acc[m][n] = 0ull;
                float sim   = lo + hi;
                float logit = sim * 10.0f;
                // exp(logit - 10) via ex2 (max logit = 10 -> fixed shift, no online max)
                float e;
                float arg = fmaf(logit, LOG2E, -10.0f * LOG2E);
                asm("ex2.approx.ftz.f32 %0, %1;" : "=f"(e) : "f"(arg));
                bool self = (gi == gj);
                float dot3 = pa.x * pb.x + pa.y * pb.y + pa.z * pb.z;
                float d2   = pa.w + pb.w - 2.0f * dot3;
                bool ispos = (d2 < EPS2) && !self;
                se[m]  += self  ? 0.0f : e;
                sp[m]  += ispos ? logit : 0.0f;
                cnt[m] += ispos ? 1.0f : 0.0f;
            }
        }
        __syncthreads();
    }

    // ---- reduce across the 16 column lanes sharing each row ----
    #pragma unroll
    for (int m = 0; m < 4; m++) {
        float a = se[m], b = sp[m], c = cnt[m];
        #pragma unroll
        for (int o = 8; o; o >>= 1) {
            a += __shfl_down_sync(0xffffffffu, a, o, 16);
            b += __shfl_down_sync(0xffffffffu, b, o, 16);
            c += __shfl_down_sync(0xffffffffu, c, o, 16);
        }
        if (tx == 0) {
            int gi = rowBase + m * 16 + ty;
            g_se[split * N + gi]  = a;
            g_sp[split * N + gi]  = b;
            g_cnt[split * N + gi] = c;
        }
    }
}

// ---------------- final stage 1: 32 blocks, per-anchor loss, block partials ----------------
__global__ void final_partial_kernel() {
    __shared__ float sL[256], sV[256];
    int tid = threadIdx.x;
    int r = blockIdx.x * 256 + tid;            // 32 * 256 = 8192 anchors
    float se = 0.f, sp = 0.f, c = 0.f;
    #pragma unroll 1
    for (int s = 0; s < NSPLIT; s++) {
        se += g_se[s * N + r];
        sp += g_sp[s * N + r];
        c  += g_cnt[s * N + r];
    }
    float lse = logf(se) + 10.0f;              // undo the fixed shift
    float L = 0.f, V = 0.f;
    if (c > 0.0f) { L = -(sp - c * lse) / c; V = 1.0f; }
    sL[tid] = L; sV[tid] = V;
    __syncthreads();
    #pragma unroll
    for (int o = 128; o; o >>= 1) {
        if (tid < o) { sL[tid] += sL[tid + o]; sV[tid] += sV[tid + o]; }
        __syncthreads();
    }
    if (tid == 0) { g_partL[blockIdx.x] = sL[0]; g_partV[blockIdx.x] = sV[0]; }
}

// ---------------- final stage 2: combine 32 partials ----------------
__global__ void final_combine_kernel(float* __restrict__ out) {
    int tid = threadIdx.x;                     // 32 threads
    float a = g_partL[tid], b = g_partV[tid];
    #pragma unroll
    for (int o = 16; o; o >>= 1) {
        a += __shfl_down_sync(0xffffffffu, a, o);
        b += __shfl_down_sync(0xffffffffu, b, o);
    }
    if (tid == 0) out[0] = a / fmaxf(b, 1.0f);
}

// ---------------- launch ----------------
extern "C" void kernel_launch(void* const* d_in, const int* in_sizes, int n_in,
                              void* d_out, int out_size) {
    const float* h   = (const float*)d_in[0];
    const float* pos = (const float*)d_in[1];
    if (n_in >= 2 && in_sizes[0] < in_sizes[1]) {  // defensive: h is the big one
        const float* t = h; h = pos; pos = t;
    }
    float* out = (float*)d_out;

    normalize_kernel<<<N / 8, 256>>>(h);
    pos_kernel<<<N / 256, 256>>>(pos);

    cudaFuncSetAttribute(main_kernel, cudaFuncAttributeMaxDynamicSharedMemorySize, SMEM_MAIN);
    dim3 grid(N / BM, NSPLIT);
    main_kernel<<<grid, 256, SMEM_MAIN>>>();

    final_partial_kernel<<<32, 256>>>();
    final_combine_kernel<<<1, 32>>>(out);
}

// round 6
// speedup vs baseline: 5.8577x; 2.4738x over previous
#include <cuda_runtime.h>
#include <cuda_bf16.h>
#include <cstdint>

#define N 8192
#define D 128
#define NBLK 64              // 64 tiles of 128 rows/cols
#define TILEB 32768          // 128x128 bf16 tile bytes
#define NSPLIT 16            // column splits
#define TPS 4                // tiles per split (64/16)
#define NSLOT 64             // NSPLIT * 4 warp-column slots
#define EPS2 0.25f
#define LOG2E 1.4426950408889634f

// ---------------- device scratch ----------------
__device__ uint4  g_hi[NBLK * 2048];   // bf16 hi tiles, ldmatrix-swizzled
__device__ uint4  g_lo[NBLK * 2048];   // bf16 lo tiles
__device__ float4 g_pos4[N];           // (x,y,z,|p|^2)
__device__ float  g_se[NSLOT * N], g_sp[NSLOT * N], g_cnt[NSLOT * N];
__device__ float  g_partL[64], g_partV[64];

// ---------------- portable PTX helpers (plain sm_103 target legal) ----------------
#define CP16(dst, src) \
    asm volatile("cp.async.cg.shared.global [%0], [%1], 16;\n" :: "r"(dst), "l"(src) : "memory")
#define CP_COMMIT() asm volatile("cp.async.commit_group;\n" ::: "memory")
#define CP_WAIT0()  asm volatile("cp.async.wait_group 0;\n" ::: "memory")

#define LDSM4(r0, r1, r2, r3, addr) \
    asm volatile("ldmatrix.sync.aligned.m8n8.x4.shared.b16 {%0,%1,%2,%3}, [%4];" \
                 : "=r"(r0), "=r"(r1), "=r"(r2), "=r"(r3) : "r"(addr))

#define MMA16816(d, a, b0, b1) \
    asm volatile("mma.sync.aligned.m16n8k16.row.col.f32.bf16.bf16.f32 " \
                 "{%0,%1,%2,%3}, {%4,%5,%6,%7}, {%8,%9}, {%0,%1,%2,%3};" \
                 : "+f"((d)[0]), "+f"((d)[1]), "+f"((d)[2]), "+f"((d)[3]) \
                 : "r"((a)[0]), "r"((a)[1]), "r"((a)[2]), "r"((a)[3]), "r"(b0), "r"(b1))

// XOR swizzle: 16B-chunk index within a 256B row, conflict-free for 8-row ldmatrix
__device__ __host__ __forceinline__ uint32_t swz(uint32_t x, uint32_t c16) {
    return (c16 & 8u) | ((c16 & 7u) ^ x);
}

// ---------------- prep: normalize + bf16 split + swizzled tile store ----------------
__global__ void prep_kernel(const float* __restrict__ h) {
    int row  = blockIdx.x * 8 + (threadIdx.x >> 5);
    int lane = threadIdx.x & 31;
    float4 v = ((const float4*)h)[row * 32 + lane];   // 4 k-values: k = lane*4..+3
    float ss = v.x * v.x + v.y * v.y + v.z * v.z + v.w * v.w;
    #pragma unroll
    for (int o = 16; o; o >>= 1) ss += __shfl_xor_sync(0xffffffffu, ss, o);
    float inv = 1.0f / fmaxf(sqrtf(ss), 1e-12f);
    float x[4] = {v.x * inv, v.y * inv, v.z * inv, v.w * inv};
    unsigned short hb[4], lb[4];
    #pragma unroll
    for (int j = 0; j < 4; j++) {
        __nv_bfloat16 hh = __float2bfloat16(x[j]);
        __nv_bfloat16 ll = __float2bfloat16(x[j] - __bfloat162float(hh));
        hb[j] = __bfloat16_as_ushort(hh);
        lb[j] = __bfloat16_as_ushort(ll);
    }
    uint2 hu = make_uint2((uint32_t)hb[0] | ((uint32_t)hb[1] << 16),
                          (uint32_t)hb[2] | ((uint32_t)hb[3] << 16));
    uint2 lu = make_uint2((uint32_t)lb[0] | ((uint32_t)lb[1] << 16),
                          (uint32_t)lb[2] | ((uint32_t)lb[3] << 16));
    int blk = row >> 7, r = row & 127;
    uint32_t c16 = (uint32_t)(lane >> 1);             // byte col = lane*8 -> /16
    uint32_t soff = (uint32_t)r * 256u + swz((uint32_t)(r & 7), c16) * 16u
                    + (uint32_t)(lane & 1) * 8u;
    *(uint2*)((char*)g_hi + (size_t)blk * TILEB + soff) = hu;
    *(uint2*)((char*)g_lo + (size_t)blk * TILEB + soff) = lu;
}

__global__ void pos_kernel(const float* __restrict__ pos) {
    int i = blockIdx.x * blockDim.x + threadIdx.x;
    if (i < N) {
        float x = pos[3 * i], y = pos[3 * i + 1], z = pos[3 * i + 2];
        g_pos4[i] = make_float4(x, y, z, x * x + y * y + z * z);
    }
}

// ---------------- main kernel ----------------
// smem: AHI 0..32K | ALO 32K..64K | B[0] hi 64K lo 96K | B[1] hi 128K lo 160K
#define AHI 0
#define ALO 32768
#define BB(b) (65536 + (b) * 65536)
#define SMEM_REQ 196608

__global__ void __launch_bounds__(256, 1) main_kernel() {
    extern __shared__ __align__(128) char smem[];
    const uint32_t sbase = (uint32_t)__cvta_generic_to_shared(smem);

    const int tid = threadIdx.x, wid = tid >> 5, lane = tid & 31;
    const int rowBlk = blockIdx.x, split = blockIdx.y;
    const int t0 = split * TPS;
    const int rowBase = rowBlk * 128;
    const int warpRow = wid >> 2, warpCol = wid & 3;

    // ---- prologue: A hi/lo + B[0] hi/lo ----
    {
        const char* ga  = (const char*)g_hi + (size_t)rowBlk * TILEB;
        const char* gal = (const char*)g_lo + (size_t)rowBlk * TILEB;
        const char* gb  = (const char*)g_hi + (size_t)t0 * TILEB;
        const char* gbl = (const char*)g_lo + (size_t)t0 * TILEB;
        #pragma unroll
        for (int i = 0; i < 8; i++) {
            uint32_t o = (uint32_t)(tid * 128 + i * 16);
            CP16(sbase + AHI + o, ga + o);
            CP16(sbase + ALO + o, gal + o);
            CP16(sbase + BB(0) + o, gb + o);
            CP16(sbase + BB(0) + 32768 + o, gbl + o);
        }
        CP_COMMIT();
    }

    // ---- per-lane constants ----
    // A row addresses: lanes 0-7 rows m..m+7 @k, 8-15 m+8..15 @k, 16-23 m..7 @k+8, 24-31 m+8..15 @k+8
    uint32_t aAddr[4], axr[4];
    #pragma unroll
    for (int mt = 0; mt < 4; mt++) {
        uint32_t r = (uint32_t)(warpRow * 64 + mt * 16 + (lane & 15));
        aAddr[mt] = sbase + AHI + r * 256u;
        axr[mt]   = r & 7u;
    }
    const uint32_t aSel = (uint32_t)((lane >> 4) & 1);
    // B row (=n) addresses: lanes 0-7 n..n+7 @k, 8-15 n..n+7 @k+8, 16-23 n+8..15 @k, 24-31 n+8..15 @k+8
    uint32_t bOff[2], bxr[2];
    #pragma unroll
    for (int ntp = 0; ntp < 2; ntp++) {
        uint32_t n = (uint32_t)(warpCol * 32 + ntp * 16 + ((lane >> 4) & 1) * 8 + (lane & 7));
        bOff[ntp] = n * 256u;
        bxr[ntp]  = n & 7u;
    }
    const uint32_t bSel = (uint32_t)((lane >> 3) & 1);

    // anchor positions for this lane's 8 rows (fixed for the CTA)
    float4 pa[8];
    #pragma unroll
    for (int mt = 0; mt < 4; mt++)
        #pragma unroll
        for (int rs = 0; rs < 2; rs++)
            pa[mt * 2 + rs] = __ldg(&g_pos4[rowBase + warpRow * 64 + mt * 16 + (lane >> 2) + rs * 8]);

    float se[8], sp[8], ct[8];
    #pragma unroll
    for (int i = 0; i < 8; i++) { se[i] = 0.f; sp[i] = 0.f; ct[i] = 0.f; }

    float acc[4][4][4];

    for (int tt = 0; tt < TPS; tt++) {
        const int buf = tt & 1;
        CP_WAIT0();
        __syncthreads();

        // prefetch next B into the other buffer
        if (tt + 1 < TPS) {
            const char* gb  = (const char*)g_hi + (size_t)(t0 + tt + 1) * TILEB;
            const char* gbl = (const char*)g_lo + (size_t)(t0 + tt + 1) * TILEB;
            #pragma unroll
            for (int i = 0; i < 8; i++) {
                uint32_t o = (uint32_t)(tid * 128 + i * 16);
                CP16(sbase + BB(buf ^ 1) + o, gb + o);
                CP16(sbase + BB(buf ^ 1) + 32768 + o, gbl + o);
            }
            CP_COMMIT();
        }

        #pragma unroll
        for (int mt = 0; mt < 4; mt++)
            #pragma unroll
            for (int nt = 0; nt < 4; nt++)
                #pragma unroll
                for (int c = 0; c < 4; c++) acc[mt][nt][c] = 0.f;

        const uint32_t baseBH = sbase + BB(buf);
        const uint32_t baseBL = baseBH + 32768u;

        #pragma unroll 2
        for (int step = 0; step < 8; step++) {
            const uint32_t c16a = (uint32_t)(2 * step) + aSel;
            const uint32_t c16b = (uint32_t)(2 * step) + bSel;
            uint32_t bh[2][4], bl[2][4], af[4][4];
            #pragma unroll
            for (int ntp = 0; ntp < 2; ntp++) {
                uint32_t sw = swz(bxr[ntp], c16b) << 4;
                LDSM4(bh[ntp][0], bh[ntp][1], bh[ntp][2], bh[ntp][3], baseBH + bOff[ntp] + sw);
            }
            #pragma unroll
            for (int mt = 0; mt < 4; mt++) {
                uint32_t sw = swz(axr[mt], c16a) << 4;
                LDSM4(af[mt][0], af[mt][1], af[mt][2], af[mt][3], aAddr[mt] + sw);
            }
            // pass 1: Ahi * Bhi
            #pragma unroll
            for (int mt = 0; mt < 4; mt++)
                #pragma unroll
                for (int nt = 0; nt < 4; nt++)
                    MMA16816(acc[mt][nt], af[mt], bh[nt >> 1][(nt & 1) * 2], bh[nt >> 1][(nt & 1) * 2 + 1]);
            // pass 2: Ahi * Blo
            #pragma unroll
            for (int ntp = 0; ntp < 2; ntp++) {
                uint32_t sw = swz(bxr[ntp], c16b) << 4;
                LDSM4(bl[ntp][0], bl[ntp][1], bl[ntp][2], bl[ntp][3], baseBL + bOff[ntp] + sw);
            }
            #pragma unroll
            for (int mt = 0; mt < 4; mt++)
                #pragma unroll
                for (int nt = 0; nt < 4; nt++)
                    MMA16816(acc[mt][nt], af[mt], bl[nt >> 1][(nt & 1) * 2], bl[nt >> 1][(nt & 1) * 2 + 1]);
            // pass 3: Alo * Bhi
            #pragma unroll
            for (int mt = 0; mt < 4; mt++) {
                uint32_t sw = swz(axr[mt], c16a) << 4;
                LDSM4(af[mt][0], af[mt][1], af[mt][2], af[mt][3], aAddr[mt] + 32768u + sw);
            }
            #pragma unroll
            for (int mt = 0; mt < 4; mt++)
                #pragma unroll
                for (int nt = 0; nt < 4; nt++)
                    MMA16816(acc[mt][nt], af[mt], bh[nt >> 1][(nt & 1) * 2], bh[nt >> 1][(nt & 1) * 2 + 1]);
        }

        // ---- epilogue: fold this tile's 64 sims into per-lane row accumulators ----
        const int ctile = t0 + tt;
        float4 pb[8];
        #pragma unroll
        for (int nt = 0; nt < 4; nt++)
            #pragma unroll
            for (int ce = 0; ce < 2; ce++)
                pb[nt * 2 + ce] = __ldg(&g_pos4[ctile * 128 + warpCol * 32 + nt * 8 + (lane & 3) * 2 + ce]);

        #pragma unroll
        for (int mt = 0; mt < 4; mt++) {
            #pragma unroll
            for (int rs = 0; rs < 2; rs++) {
                const int idx = mt * 2 + rs;
                const float4 A = pa[idx];
                const int gi = rowBase + warpRow * 64 + mt * 16 + (lane >> 2) + rs * 8;
                #pragma unroll
                for (int nt = 0; nt < 4; nt++) {
                    #pragma unroll
                    for (int ce = 0; ce < 2; ce++) {
                        float sim   = acc[mt][nt][rs * 2 + ce];
                        int j = ctile * 128 + warpCol * 32 + nt * 8 + (lane & 3) * 2 + ce;
                        float logit = 10.0f * sim;
                        float e, arg = fmaf(logit, LOG2E, -10.0f * LOG2E);
                        asm("ex2.approx.ftz.f32 %0, %1;" : "=f"(e) : "f"(arg));
                        float4 B = pb[nt * 2 + ce];
                        bool self = (gi == j);
                        float dot = A.x * B.x + A.y * B.y + A.z * B.z;
                        float d2  = A.w + B.w - 2.0f * dot;
                        bool ispos = (d2 < EPS2) && !self;
                        se[idx] += self  ? 0.0f : e;
                        sp[idx] += ispos ? logit : 0.0f;
                        ct[idx] += ispos ? 1.0f : 0.0f;
                    }
                }
            }
        }
    }

    // ---- reduce across the 4 lanes (lane&3) sharing each row; write slot ----
    const int slot = split * 4 + warpCol;
    #pragma unroll
    for (int idx = 0; idx < 8; idx++) {
        float a = se[idx], b = sp[idx], c = ct[idx];
        a += __shfl_down_sync(0xffffffffu, a, 2, 4);
        b += __shfl_down_sync(0xffffffffu, b, 2, 4);
        c += __shfl_down_sync(0xffffffffu, c, 2, 4);
        a += __shfl_down_sync(0xffffffffu, a, 1, 4);
        b += __shfl_down_sync(0xffffffffu, b, 1, 4);
        c += __shfl_down_sync(0xffffffffu, c, 1, 4);
        if ((lane & 3) == 0) {
            int gi = rowBase + warpRow * 64 + (idx >> 1) * 16 + (lane >> 2) + (idx & 1) * 8;
            g_se[slot * N + gi]  = a;
            g_sp[slot * N + gi]  = b;
            g_cnt[slot * N + gi] = c;
        }
    }
}

// ---------------- final reduction ----------------
__global__ void final_partial_kernel() {
    __shared__ float sL[4], sV[4];
    int tid = threadIdx.x, wid = tid >> 5, lane = tid & 31;
    int r = blockIdx.x * 128 + tid;
    float se = 0.f, sp = 0.f, c = 0.f;
    #pragma unroll 8
    for (int s = 0; s < NSLOT; s++) {
        se += g_se[s * N + r]; sp += g_sp[s * N + r]; c += g_cnt[s * N + r];
    }
    float lse = logf(se) + 10.0f;
    float L = 0.f, V = 0.f;
    if (c > 0.0f) { L = -(sp - c * lse) / c; V = 1.0f; }
    #pragma unroll
    for (int o = 16; o; o >>= 1) {
        L += __shfl_down_sync(0xffffffffu, L, o);
        V += __shfl_down_sync(0xffffffffu, V, o);
    }
    if (lane == 0) { sL[wid] = L; sV[wid] = V; }
    __syncthreads();
    if (tid == 0) {
        g_partL[blockIdx.x] = sL[0] + sL[1] + sL[2] + sL[3];
        g_partV[blockIdx.x] = sV[0] + sV[1] + sV[2] + sV[3];
    }
}

__global__ void final_combine_kernel(float* __restrict__ out) {
    int tid = threadIdx.x;   // 32 threads
    float a = g_partL[tid] + g_partL[tid + 32];
    float b = g_partV[tid] + g_partV[tid + 32];
    #pragma unroll
    for (int o = 16; o; o >>= 1) {
        a += __shfl_down_sync(0xffffffffu, a, o);
        b += __shfl_down_sync(0xffffffffu, b, o);
    }
    if (tid == 0) out[0] = a / fmaxf(b, 1.0f);
}

// ---------------- launch ----------------
extern "C" void kernel_launch(void* const* d_in, const int* in_sizes, int n_in,
                              void* d_out, int out_size) {
    const float* h   = (const float*)d_in[0];
    const float* pos = (const float*)d_in[1];
    if (n_in >= 2 && in_sizes[0] < in_sizes[1]) {
        const float* t = h; h = pos; pos = t;
    }
    float* out = (float*)d_out;

    prep_kernel<<<N / 8, 256>>>(h);
    pos_kernel<<<N / 256, 256>>>(pos);

    cudaFuncSetAttribute(main_kernel, cudaFuncAttributeMaxDynamicSharedMemorySize, SMEM_REQ);
    dim3 grid(NBLK, NSPLIT);
    main_kernel<<<grid, 256, SMEM_REQ>>>();

    final_partial_kernel<<<64, 128>>>();
    final_combine_kernel<<<1, 32>>>(out);
}

// round 7
// speedup vs baseline: 7.7545x; 1.3238x over previous
#include <cuda_runtime.h>
#include <cuda_bf16.h>
#include <cstdint>

#define N 8192
#define D 128
#define NBLK 64               // 64 tiles of 128 rows/cols
#define TILEB 32768           // 128x128 bf16 tile bytes
#define NCTA 2080             // upper-triangle tile pairs (64*65/2)
#define EPS2 0.25f
#define LOG2E 1.4426950408889634f

// ---------------- device scratch ----------------
__device__ uint4  g_hi[NBLK * 2048];   // bf16 hi tiles, ldmatrix-swizzled
__device__ uint4  g_lo[NBLK * 2048];   // bf16 lo tiles
__device__ float4 g_pos4[N];           // (x,y,z,|p|^2)
__device__ float  g_dse[NCTA * 128], g_dsp[NCTA * 128], g_dct[NCTA * 128];  // row (block I) partials
__device__ float  g_tse[NCTA * 128], g_tsp[NCTA * 128], g_tct[NCTA * 128];  // col (block J) partials
__device__ float  g_partL[64], g_partV[64];

// ---------------- portable PTX helpers ----------------
#define CP16(dst, src) \
    asm volatile("cp.async.cg.shared.global [%0], [%1], 16;\n" :: "r"(dst), "l"(src) : "memory")
#define CP_COMMIT() asm volatile("cp.async.commit_group;\n" ::: "memory")
#define CP_WAIT0()  asm volatile("cp.async.wait_group 0;\n" ::: "memory")

#define LDSM4(r0, r1, r2, r3, addr) \
    asm volatile("ldmatrix.sync.aligned.m8n8.x4.shared.b16 {%0,%1,%2,%3}, [%4];" \
                 : "=r"(r0), "=r"(r1), "=r"(r2), "=r"(r3) : "r"(addr))

#define MMA16816(d, a, b0, b1) \
    asm volatile("mma.sync.aligned.m16n8k16.row.col.f32.bf16.bf16.f32 " \
                 "{%0,%1,%2,%3}, {%4,%5,%6,%7}, {%8,%9}, {%0,%1,%2,%3};" \
                 : "+f"((d)[0]), "+f"((d)[1]), "+f"((d)[2]), "+f"((d)[3]) \
                 : "r"((a)[0]), "r"((a)[1]), "r"((a)[2]), "r"((a)[3]), "r"(b0), "r"(b1))

__device__ __host__ __forceinline__ uint32_t swz(uint32_t x, uint32_t c16) {
    return (c16 & 8u) | ((c16 & 7u) ^ x);
}

// ---------------- prep: normalize + bf16 split + swizzled tile store ----------------
__global__ void prep_kernel(const float* __restrict__ h) {
    int row  = blockIdx.x * 8 + (threadIdx.x >> 5);
    int lane = threadIdx.x & 31;
    float4 v = ((const float4*)h)[row * 32 + lane];
    float ss = v.x * v.x + v.y * v.y + v.z * v.z + v.w * v.w;
    #pragma unroll
    for (int o = 16; o; o >>= 1) ss += __shfl_xor_sync(0xffffffffu, ss, o);
    float inv = 1.0f / fmaxf(sqrtf(ss), 1e-12f);
    float x[4] = {v.x * inv, v.y * inv, v.z * inv, v.w * inv};
    unsigned short hb[4], lb[4];
    #pragma unroll
    for (int j = 0; j < 4; j++) {
        __nv_bfloat16 hh = __float2bfloat16(x[j]);
        __nv_bfloat16 ll = __float2bfloat16(x[j] - __bfloat162float(hh));
        hb[j] = __bfloat16_as_ushort(hh);
        lb[j] = __bfloat16_as_ushort(ll);
    }
    uint2 hu = make_uint2((uint32_t)hb[0] | ((uint32_t)hb[1] << 16),
                          (uint32_t)hb[2] | ((uint32_t)hb[3] << 16));
    uint2 lu = make_uint2((uint32_t)lb[0] | ((uint32_t)lb[1] << 16),
                          (uint32_t)lb[2] | ((uint32_t)lb[3] << 16));
    int blk = row >> 7, r = row & 127;
    uint32_t c16 = (uint32_t)(lane >> 1);
    uint32_t soff = (uint32_t)r * 256u + swz((uint32_t)(r & 7), c16) * 16u
                    + (uint32_t)(lane & 1) * 8u;
    *(uint2*)((char*)g_hi + (size_t)blk * TILEB + soff) = hu;
    *(uint2*)((char*)g_lo + (size_t)blk * TILEB + soff) = lu;
}

__global__ void pos_kernel(const float* __restrict__ pos) {
    int i = blockIdx.x * blockDim.x + threadIdx.x;
    if (i < N) {
        float x = pos[3 * i], y = pos[3 * i + 1], z = pos[3 * i + 2];
        g_pos4[i] = make_float4(x, y, z, x * x + y * y + z * z);
    }
}

// ---------------- main kernel: one upper-triangle tile pair per CTA ----------------
// smem: AHI 0 | ALO 32K | BHI 64K | BLO 96K | red buffers @128K
#define AHI 0
#define ALO 32768
#define BHI 65536
#define BLO 98304
#define RED 131072            // rbuf: 3 x [8][64] floats (6144B), cbuf: 3 x [8][32] (3072B)
#define SMEM_REQ (RED + 9216)

__global__ void __launch_bounds__(256, 1) main_kernel() {
    extern __shared__ __align__(128) char smem[];
    const uint32_t sbase = (uint32_t)__cvta_generic_to_shared(smem);
    float* rbuf_se = (float*)(smem + RED);
    float* rbuf_sp = rbuf_se + 512;
    float* rbuf_ct = rbuf_sp + 512;
    float* cbuf_se = rbuf_ct + 512;
    float* cbuf_sp = cbuf_se + 256;
    float* cbuf_ct = cbuf_sp + 256;

    const int tid = threadIdx.x, wid = tid >> 5, lane = tid & 31;
    const int warpRow = wid >> 2, warpCol = wid & 3;

    // map linear CTA id -> (I, J), I <= J (upper triangle)
    int t = blockIdx.x, I = 0;
    while (t >= NBLK - I) { t -= NBLK - I; I++; }
    const int J = I + t;
    const bool diag = (I == J);
    const int rowBase = I * 128, colBase0 = J * 128;

    // ---- loads: A = tile I (hi+lo); B = tile J (hi+lo) unless diag ----
    {
        const char* ga  = (const char*)g_hi + (size_t)I * TILEB;
        const char* gal = (const char*)g_lo + (size_t)I * TILEB;
        #pragma unroll
        for (int i = 0; i < 8; i++) {
            uint32_t o = (uint32_t)(tid * 128 + i * 16);
            CP16(sbase + AHI + o, ga + o);
            CP16(sbase + ALO + o, gal + o);
        }
        if (!diag) {
            const char* gb  = (const char*)g_hi + (size_t)J * TILEB;
            const char* gbl = (const char*)g_lo + (size_t)J * TILEB;
            #pragma unroll
            for (int i = 0; i < 8; i++) {
                uint32_t o = (uint32_t)(tid * 128 + i * 16);
                CP16(sbase + BHI + o, gb + o);
                CP16(sbase + BLO + o, gbl + o);
            }
        }
        CP_COMMIT();
    }

    // ---- fragment address constants ----
    uint32_t aAddr[4], axr[4];
    #pragma unroll
    for (int mt = 0; mt < 4; mt++) {
        uint32_t r = (uint32_t)(warpRow * 64 + mt * 16 + (lane & 15));
        aAddr[mt] = sbase + AHI + r * 256u;
        axr[mt]   = r & 7u;
    }
    const uint32_t aSel = (uint32_t)((lane >> 4) & 1);
    uint32_t bOff[2], bxr[2];
    #pragma unroll
    for (int ntp = 0; ntp < 2; ntp++) {
        uint32_t n = (uint32_t)(warpCol * 32 + ntp * 16 + ((lane >> 4) & 1) * 8 + (lane & 7));
        bOff[ntp] = n * 256u;
        bxr[ntp]  = n & 7u;
    }
    const uint32_t bSel = (uint32_t)((lane >> 3) & 1);

    const uint32_t baseBH = diag ? (sbase + AHI) : (sbase + BHI);
    const uint32_t baseBL = diag ? (sbase + ALO) : (sbase + BLO);

    float acc[4][4][4];
    #pragma unroll
    for (int mt = 0; mt < 4; mt++)
        #pragma unroll
        for (int nt = 0; nt < 4; nt++)
            #pragma unroll
            for (int c = 0; c < 4; c++) acc[mt][nt][c] = 0.f;

    CP_WAIT0();
    __syncthreads();

    // ---- 3-pass split GEMM: hi*hi + hi*lo + lo*hi ----
    #pragma unroll 2
    for (int step = 0; step < 8; step++) {
        const uint32_t c16a = (uint32_t)(2 * step) + aSel;
        const uint32_t c16b = (uint32_t)(2 * step) + bSel;
        uint32_t bh[2][4], bl[2][4], af[4][4];
        #pragma unroll
        for (int ntp = 0; ntp < 2; ntp++) {
            uint32_t sw = swz(bxr[ntp], c16b) << 4;
            LDSM4(bh[ntp][0], bh[ntp][1], bh[ntp][2], bh[ntp][3], baseBH + bOff[ntp] + sw);
        }
        #pragma unroll
        for (int mt = 0; mt < 4; mt++) {
            uint32_t sw = swz(axr[mt], c16a) << 4;
            LDSM4(af[mt][0], af[mt][1], af[mt][2], af[mt][3], aAddr[mt] + sw);
        }
        #pragma unroll
        for (int mt = 0; mt < 4; mt++)
            #pragma unroll
            for (int nt = 0; nt < 4; nt++)
                MMA16816(acc[mt][nt], af[mt], bh[nt >> 1][(nt & 1) * 2], bh[nt >> 1][(nt & 1) * 2 + 1]);
        #pragma unroll
        for (int ntp = 0; ntp < 2; ntp++) {
            uint32_t sw = swz(bxr[ntp], c16b) << 4;
            LDSM4(bl[ntp][0], bl[ntp][1], bl[ntp][2], bl[ntp][3], baseBL + bOff[ntp] + sw);
        }
        #pragma unroll
        for (int mt = 0; mt < 4; mt++)
            #pragma unroll
            for (int nt = 0; nt < 4; nt++)
                MMA16816(acc[mt][nt], af[mt], bl[nt >> 1][(nt & 1) * 2], bl[nt >> 1][(nt & 1) * 2 + 1]);
        #pragma unroll
        for (int mt = 0; mt < 4; mt++) {
            uint32_t sw = swz(axr[mt], c16a) << 4;
            LDSM4(af[mt][0], af[mt][1], af[mt][2], af[mt][3], aAddr[mt] + 32768u + sw);
        }
        #pragma unroll
        for (int mt = 0; mt < 4; mt++)
            #pragma unroll
            for (int nt = 0; nt < 4; nt++)
                MMA16816(acc[mt][nt], af[mt], bh[nt >> 1][(nt & 1) * 2], bh[nt >> 1][(nt & 1) * 2 + 1]);
    }

    // ---- epilogue: fold into row (block I) AND column (block J) accumulators ----
    float rse[8], rsp[8], rct[8], cse[8], csp[8], cct[8];
    #pragma unroll
    for (int i = 0; i < 8; i++) {
        rse[i] = 0.f; rsp[i] = 0.f; rct[i] = 0.f;
        cse[i] = 0.f; csp[i] = 0.f; cct[i] = 0.f;
    }
    float4 pb[8];
    #pragma unroll
    for (int nt = 0; nt < 4; nt++)
        #pragma unroll
        for (int ce = 0; ce < 2; ce++)
            pb[nt * 2 + ce] = __ldg(&g_pos4[colBase0 + warpCol * 32 + nt * 8 + (lane & 3) * 2 + ce]);

    #pragma unroll
    for (int mt = 0; mt < 4; mt++) {
        #pragma unroll
        for (int rs = 0; rs < 2; rs++) {
            const int idx = mt * 2 + rs;
            const int gi = rowBase + warpRow * 64 + mt * 16 + (lane >> 2) + rs * 8;
            const float4 A = __ldg(&g_pos4[gi]);
            #pragma unroll
            for (int nt = 0; nt < 4; nt++) {
                #pragma unroll
                for (int ce = 0; ce < 2; ce++) {
                    float sim   = acc[mt][nt][rs * 2 + ce];
                    int j = colBase0 + warpCol * 32 + nt * 8 + (lane & 3) * 2 + ce;
                    float logit = 10.0f * sim;
                    float e, arg = fmaf(logit, LOG2E, -10.0f * LOG2E);
                    asm("ex2.approx.ftz.f32 %0, %1;" : "=f"(e) : "f"(arg));
                    float4 B = pb[nt * 2 + ce];
                    bool self = (gi == j);
                    float dot = A.x * B.x + A.y * B.y + A.z * B.z;
                    float d2  = A.w + B.w - 2.0f * dot;
                    bool ispos = (d2 < EPS2) && !self;
                    float ev = self ? 0.0f : e;
                    float pv = ispos ? logit : 0.0f;
                    float cv = ispos ? 1.0f : 0.0f;
                    rse[idx] += ev; rsp[idx] += pv; rct[idx] += cv;
                    int cidx = nt * 2 + ce;
                    cse[cidx] += ev; csp[cidx] += pv; cct[cidx] += cv;
                }
            }
        }
    }

    // ---- row reduce: over 4 lanes (lane&3) sharing each row ----
    #pragma unroll
    for (int idx = 0; idx < 8; idx++) {
        float a = rse[idx], b = rsp[idx], c = rct[idx];
        a += __shfl_down_sync(0xffffffffu, a, 2, 4);
        b += __shfl_down_sync(0xffffffffu, b, 2, 4);
        c += __shfl_down_sync(0xffffffffu, c, 2, 4);
        a += __shfl_down_sync(0xffffffffu, a, 1, 4);
        b += __shfl_down_sync(0xffffffffu, b, 1, 4);
        c += __shfl_down_sync(0xffffffffu, c, 1, 4);
        if ((lane & 3) == 0) {
            int rl = (idx >> 1) * 16 + (lane >> 2) + (idx & 1) * 8;   // 0..63 within half
            rbuf_se[wid * 64 + rl] = a;
            rbuf_sp[wid * 64 + rl] = b;
            rbuf_ct[wid * 64 + rl] = c;
        }
    }
    // ---- col reduce: over 8 lanes (lane>>2) sharing each column ----
    #pragma unroll
    for (int cidx = 0; cidx < 8; cidx++) {
        float a = cse[cidx], b = csp[cidx], c = cct[cidx];
        #pragma unroll
        for (int o = 16; o >= 4; o >>= 1) {
            a += __shfl_down_sync(0xffffffffu, a, o);
            b += __shfl_down_sync(0xffffffffu, b, o);
            c += __shfl_down_sync(0xffffffffu, c, o);
        }
        if (lane < 4) {
            int cl = (cidx >> 1) * 8 + lane * 2 + (cidx & 1);          // 0..31 within warp cols
            cbuf_se[wid * 32 + cl] = a;
            cbuf_sp[wid * 32 + cl] = b;
            cbuf_ct[wid * 32 + cl] = c;
        }
    }
    __syncthreads();

    // ---- combine across warps, write global slots ----
    const int slot = blockIdx.x * 128;
    if (tid < 128) {                       // rows: sum the 4 warpCols of this half
        int half = tid >> 6, loc = tid & 63;
        float a = 0.f, b = 0.f, c = 0.f;
        #pragma unroll
        for (int wc = 0; wc < 4; wc++) {
            int w = half * 4 + wc;
            a += rbuf_se[w * 64 + loc];
            b += rbuf_sp[w * 64 + loc];
            c += rbuf_ct[w * 64 + loc];
        }
        g_dse[slot + tid] = a; g_dsp[slot + tid] = b; g_dct[slot + tid] = c;
    } else if (!diag) {                    // cols: sum the 2 warpRows
        int tcl = tid - 128, wc = tcl >> 5, c5 = tcl & 31;
        float a = cbuf_se[wc * 32 + c5] + cbuf_se[(4 + wc) * 32 + c5];
        float b = cbuf_sp[wc * 32 + c5] + cbuf_sp[(4 + wc) * 32 + c5];
        float c = cbuf_ct[wc * 32 + c5] + cbuf_ct[(4 + wc) * 32 + c5];
        g_tse[slot + tcl] = a; g_tsp[slot + tcl] = b; g_tct[slot + tcl] = c;
    }
}

// ---------------- final reduction over triangle slots ----------------
__device__ __forceinline__ int tri_base(int I) { return I * NBLK - (I * (I - 1)) / 2; }

__global__ void final_partial_kernel() {
    __shared__ float sL[4], sV[4];
    int tid = threadIdx.x, wid = tid >> 5, lane = tid & 31;
    int r = blockIdx.x * 128 + tid;
    int R = r >> 7, rr = r & 127;
    float se = 0.f, sp = 0.f, c = 0.f;
    int idRJ = tri_base(R);                       // id(R, R)
    for (int J = R; J < NBLK; J++, idRJ++) {
        se += g_dse[idRJ * 128 + rr];
        sp += g_dsp[idRJ * 128 + rr];
        c  += g_dct[idRJ * 128 + rr];
    }
    for (int I = 0; I < R; I++) {
        int id = tri_base(I) + (R - I);
        se += g_tse[id * 128 + rr];
        sp += g_tsp[id * 128 + rr];
        c  += g_tct[id * 128 + rr];
    }
    float lse = logf(se) + 10.0f;
    float L = 0.f, V = 0.f;
    if (c > 0.0f) { L = -(sp - c * lse) / c; V = 1.0f; }
    #pragma unroll
    for (int o = 16; o; o >>= 1) {
        L += __shfl_down_sync(0xffffffffu, L, o);
        V += __shfl_down_sync(0xffffffffu, V, o);
    }
    if (lane == 0) { sL[wid] = L; sV[wid] = V; }
    __syncthreads();
    if (tid == 0) {
        g_partL[blockIdx.x] = sL[0] + sL[1] + sL[2] + sL[3];
        g_partV[blockIdx.x] = sV[0] + sV[1] + sV[2] + sV[3];
    }
}

__global__ void final_combine_kernel(float* __restrict__ out) {
    int tid = threadIdx.x;   // 32 threads
    float a = g_partL[tid] + g_partL[tid + 32];
    float b = g_partV[tid] + g_partV[tid + 32];
    #pragma unroll
    for (int o = 16; o; o >>= 1) {
        a += __shfl_down_sync(0xffffffffu, a, o);
        b += __shfl_down_sync(0xffffffffu, b, o);
    }
    if (tid == 0) out[0] = a / fmaxf(b, 1.0f);
}

// ---------------- launch ----------------
extern "C" void kernel_launch(void* const* d_in, const int* in_sizes, int n_in,
                              void* d_out, int out_size) {
    const float* h   = (const float*)d_in[0];
    const float* pos = (const float*)d_in[1];
    if (n_in >= 2 && in_sizes[0] < in_sizes[1]) {
        const float* t = h; h = pos; pos = t;
    }
    float* out = (float*)d_out;

    prep_kernel<<<N / 8, 256>>>(h);
    pos_kernel<<<N / 256, 256>>>(pos);

    cudaFuncSetAttribute(main_kernel, cudaFuncAttributeMaxDynamicSharedMemorySize, SMEM_REQ);
    main_kernel<<<NCTA, 256, SMEM_REQ>>>();

    final_partial_kernel<<<64, 128>>>();
    final_combine_kernel<<<1, 32>>>(out);
}

// round 8
// speedup vs baseline: 9.7613x; 1.2588x over previous
#include <cuda_runtime.h>
#include <cuda_bf16.h>
#include <cstdint>

#define N 8192
#define D 128
#define NBLK 64               // 64 tiles of 128 rows/cols
#define TILEB 32768           // 128x128 bf16 tile bytes
#define NCTA 2080             // upper-triangle tile pairs (64*65/2)
#define NCTAS 152             // persistent CTAs (GB300 SM count)
#define EPS2 0.25f
#define LOG2E 1.4426950408889634f

// ---------------- device scratch ----------------
__device__ uint4  g_hi[NBLK * 2048];   // bf16 hi tiles, ldmatrix-swizzled
__device__ uint4  g_lo[NBLK * 2048];   // bf16 lo tiles
__device__ float4 g_pos4[N];           // (x,y,z,|p|^2)
__device__ float  g_dse[NCTA * 128], g_dsp[NCTA * 128], g_dct[NCTA * 128];  // row (block I) partials
__device__ float  g_tse[NCTA * 128], g_tsp[NCTA * 128], g_tct[NCTA * 128];  // col (block J) partials
__device__ float  g_partL[64], g_partV[64];

// ---------------- portable PTX helpers ----------------
#define CP16(dst, src) \
    asm volatile("cp.async.cg.shared.global [%0], [%1], 16;\n" :: "r"(dst), "l"(src) : "memory")
#define CP_COMMIT() asm volatile("cp.async.commit_group;\n" ::: "memory")
#define CP_WAIT0()  asm volatile("cp.async.wait_group 0;\n" ::: "memory")

#define LDSM4(r0, r1, r2, r3, addr) \
    asm volatile("ldmatrix.sync.aligned.m8n8.x4.shared.b16 {%0,%1,%2,%3}, [%4];" \
                 : "=r"(r0), "=r"(r1), "=r"(r2), "=r"(r3) : "r"(addr))

#define MMA16816(d, a, b0, b1) \
    asm volatile("mma.sync.aligned.m16n8k16.row.col.f32.bf16.bf16.f32 " \
                 "{%0,%1,%2,%3}, {%4,%5,%6,%7}, {%8,%9}, {%0,%1,%2,%3};" \
                 : "+f"((d)[0]), "+f"((d)[1]), "+f"((d)[2]), "+f"((d)[3]) \
                 : "r"((a)[0]), "r"((a)[1]), "r"((a)[2]), "r"((a)[3]), "r"(b0), "r"(b1))

__device__ __host__ __forceinline__ uint32_t swz(uint32_t x, uint32_t c16) {
    return (c16 & 8u) | ((c16 & 7u) ^ x);
}

// ---------------- prep: normalize + bf16 split + swizzled tile store ----------------
__global__ void prep_kernel(const float* __restrict__ h) {
    int row  = blockIdx.x * 8 + (threadIdx.x >> 5);
    int lane = threadIdx.x & 31;
    float4 v = ((const float4*)h)[row * 32 + lane];
    float ss = v.x * v.x + v.y * v.y + v.z * v.z + v.w * v.w;
    #pragma unroll
    for (int o = 16; o; o >>= 1) ss += __shfl_xor_sync(0xffffffffu, ss, o);
    float inv = 1.0f / fmaxf(sqrtf(ss), 1e-12f);
    float x[4] = {v.x * inv, v.y * inv, v.z * inv, v.w * inv};
    unsigned short hb[4], lb[4];
    #pragma unroll
    for (int j = 0; j < 4; j++) {
        __nv_bfloat16 hh = __float2bfloat16(x[j]);
        __nv_bfloat16 ll = __float2bfloat16(x[j] - __bfloat162float(hh));
        hb[j] = __bfloat16_as_ushort(hh);
        lb[j] = __bfloat16_as_ushort(ll);
    }
    uint2 hu = make_uint2((uint32_t)hb[0] | ((uint32_t)hb[1] << 16),
                          (uint32_t)hb[2] | ((uint32_t)hb[3] << 16));
    uint2 lu = make_uint2((uint32_t)lb[0] | ((uint32_t)lb[1] << 16),
                          (uint32_t)lb[2] | ((uint32_t)lb[3] << 16));
    int blk = row >> 7, r = row & 127;
    uint32_t c16 = (uint32_t)(lane >> 1);
    uint32_t soff = (uint32_t)r * 256u + swz((uint32_t)(r & 7), c16) * 16u
                    + (uint32_t)(lane & 1) * 8u;
    *(uint2*)((char*)g_hi + (size_t)blk * TILEB + soff) = hu;
    *(uint2*)((char*)g_lo + (size_t)blk * TILEB + soff) = lu;
}

__global__ void pos_kernel(const float* __restrict__ pos) {
    int i = blockIdx.x * blockDim.x + threadIdx.x;
    if (i < N) {
        float x = pos[3 * i], y = pos[3 * i + 1], z = pos[3 * i + 2];
        g_pos4[i] = make_float4(x, y, z, x * x + y * y + z * z);
    }
}

// ---------------- main kernel: persistent, pipelined tile pairs ----------------
// smem: AHI 0 | ALO 32K | B buf0 (hi 64K, lo 96K) | B buf1 (hi 128K, lo 160K) | red @192K
#define AHI 0
#define ALO 32768
#define BBUF(b) (65536 + (b) * 65536)
#define RED 196608            // rbuf 3x512 floats + cbuf 3x256 floats = 9216 B
#define SMEM_REQ (RED + 9216)

__device__ __forceinline__ void load_tile32(uint32_t dstHi, uint32_t dstLo, int blk, int tid) {
    const char* gh = (const char*)g_hi + (size_t)blk * TILEB;
    const char* gl = (const char*)g_lo + (size_t)blk * TILEB;
    #pragma unroll
    for (int i = 0; i < 8; i++) {
        uint32_t o = (uint32_t)(tid * 128 + i * 16);
        CP16(dstHi + o, gh + o);
        CP16(dstLo + o, gl + o);
    }
}

__global__ void __launch_bounds__(256, 1) main_kernel() {
    extern __shared__ __align__(128) char smem[];
    const uint32_t sbase = (uint32_t)__cvta_generic_to_shared(smem);
    float* rbuf_se = (float*)(smem + RED);
    float* rbuf_sp = rbuf_se + 512;
    float* rbuf_ct = rbuf_sp + 512;
    float* cbuf_se = rbuf_ct + 512;
    float* cbuf_sp = cbuf_se + 256;
    float* cbuf_ct = cbuf_sp + 256;

    const int tid = threadIdx.x, wid = tid >> 5, lane = tid & 31;
    const int warpRow = wid >> 2, warpCol = wid & 3;

    // pair range for this persistent CTA
    const int p0 = (int)((long long)blockIdx.x * NCTA / NCTAS);
    const int p1 = (int)((long long)(blockIdx.x + 1) * NCTA / NCTAS);
    if (p0 >= p1) return;

    // decode p0 -> (I, J)
    int I = 0, t = p0;
    while (t >= NBLK - I) { t -= NBLK - I; I++; }
    int J = I + t;

    // ---- fragment address constants (A addresses fixed; B offsets fixed) ----
    uint32_t aAddr[4], axr[4];
    #pragma unroll
    for (int mt = 0; mt < 4; mt++) {
        uint32_t r = (uint32_t)(warpRow * 64 + mt * 16 + (lane & 15));
        aAddr[mt] = sbase + AHI + r * 256u;
        axr[mt]   = r & 7u;
    }
    const uint32_t aSel = (uint32_t)((lane >> 4) & 1);
    uint32_t bOff[2], bxr[2];
    #pragma unroll
    for (int ntp = 0; ntp < 2; ntp++) {
        uint32_t n = (uint32_t)(warpCol * 32 + ntp * 16 + ((lane >> 4) & 1) * 8 + (lane & 7));
        bOff[ntp] = n * 256u;
        bxr[ntp]  = n & 7u;
    }
    const uint32_t bSel = (uint32_t)((lane >> 3) & 1);

    // ---- prologue: A(I) + B(J) into buf 0 ----
    load_tile32(sbase + AHI, sbase + ALO, I, tid);
    load_tile32(sbase + BBUF(0), sbase + BBUF(0) + 32768u, J, tid);
    CP_COMMIT();

    int buf = 0;
    for (int p = p0; p < p1; p++) {
        // successor pair
        int nI = I, nJ = J + 1;
        if (nJ == NBLK) { nI = I + 1; nJ = nI; }
        const bool havenext = (p + 1 < p1);
        const bool nextSame = havenext && (nI == I);

        CP_WAIT0();
        __syncthreads();

        // prefetch next B now if A stays resident (overlaps the GEMM)
        if (nextSame) {
            load_tile32(sbase + BBUF(buf ^ 1), sbase + BBUF(buf ^ 1) + 32768u, nJ, tid);
            CP_COMMIT();
        }

        const uint32_t baseBH = sbase + BBUF(buf);
        const uint32_t baseBL = baseBH + 32768u;

        float acc[4][4][4];
        #pragma unroll
        for (int mt = 0; mt < 4; mt++)
            #pragma unroll
            for (int nt = 0; nt < 4; nt++)
                #pragma unroll
                for (int c = 0; c < 4; c++) acc[mt][nt][c] = 0.f;

        // ---- 3-pass split GEMM: hi*hi + hi*lo + lo*hi ----
        #pragma unroll 2
        for (int step = 0; step < 8; step++) {
            const uint32_t c16a = (uint32_t)(2 * step) + aSel;
            const uint32_t c16b = (uint32_t)(2 * step) + bSel;
            uint32_t bh[2][4], bl[2][4], af[4][4];
            #pragma unroll
            for (int ntp = 0; ntp < 2; ntp++) {
                uint32_t sw = swz(bxr[ntp], c16b) << 4;
                LDSM4(bh[ntp][0], bh[ntp][1], bh[ntp][2], bh[ntp][3], baseBH + bOff[ntp] + sw);
            }
            #pragma unroll
            for (int mt = 0; mt < 4; mt++) {
                uint32_t sw = swz(axr[mt], c16a) << 4;
                LDSM4(af[mt][0], af[mt][1], af[mt][2], af[mt][3], aAddr[mt] + sw);
            }
            #pragma unroll
            for (int mt = 0; mt < 4; mt++)
                #pragma unroll
                for (int nt = 0; nt < 4; nt++)
                    MMA16816(acc[mt][nt], af[mt], bh[nt >> 1][(nt & 1) * 2], bh[nt >> 1][(nt & 1) * 2 + 1]);
            #pragma unroll
            for (int ntp = 0; ntp < 2; ntp++) {
                uint32_t sw = swz(bxr[ntp], c16b) << 4;
                LDSM4(bl[ntp][0], bl[ntp][1], bl[ntp][2], bl[ntp][3], baseBL + bOff[ntp] + sw);
            }
            #pragma unroll
            for (int mt = 0; mt < 4; mt++)
                #pragma unroll
                for (int nt = 0; nt < 4; nt++)
                    MMA16816(acc[mt][nt], af[mt], bl[nt >> 1][(nt & 1) * 2], bl[nt >> 1][(nt & 1) * 2 + 1]);
            #pragma unroll
            for (int mt = 0; mt < 4; mt++) {
                uint32_t sw = swz(axr[mt], c16a) << 4;
                LDSM4(af[mt][0], af[mt][1], af[mt][2], af[mt][3], aAddr[mt] + 32768u + sw);
            }
            #pragma unroll
            for (int mt = 0; mt < 4; mt++)
                #pragma unroll
                for (int nt = 0; nt < 4; nt++)
                    MMA16816(acc[mt][nt], af[mt], bh[nt >> 1][(nt & 1) * 2], bh[nt >> 1][(nt & 1) * 2 + 1]);
        }

        __syncthreads();   // all warps done reading A and B[buf]

        // A-transition: load new A (+ next B) now, overlapping the epilogue
        if (havenext && !nextSame) {
            load_tile32(sbase + AHI, sbase + ALO, nI, tid);
            load_tile32(sbase + BBUF(buf ^ 1), sbase + BBUF(buf ^ 1) + 32768u, nJ, tid);
            CP_COMMIT();
        }

        // ---- epilogue: fold into row (block I) AND column (block J) accumulators ----
        const int rowBase = I * 128, colBase0 = J * 128;
        const bool diag = (I == J);
        float rse[8], rsp[8], rct[8], cse[8], csp[8], cct[8];
        #pragma unroll
        for (int i = 0; i < 8; i++) {
            rse[i] = 0.f; rsp[i] = 0.f; rct[i] = 0.f;
            cse[i] = 0.f; csp[i] = 0.f; cct[i] = 0.f;
        }
        float4 pb[8];
        #pragma unroll
        for (int nt = 0; nt < 4; nt++)
            #pragma unroll
            for (int ce = 0; ce < 2; ce++)
                pb[nt * 2 + ce] = __ldg(&g_pos4[colBase0 + warpCol * 32 + nt * 8 + (lane & 3) * 2 + ce]);

        #pragma unroll
        for (int mt = 0; mt < 4; mt++) {
            #pragma unroll
            for (int rs = 0; rs < 2; rs++) {
                const int idx = mt * 2 + rs;
                const int gi = rowBase + warpRow * 64 + mt * 16 + (lane >> 2) + rs * 8;
                const float4 A = __ldg(&g_pos4[gi]);
                #pragma unroll
                for (int nt = 0; nt < 4; nt++) {
                    #pragma unroll
                    for (int ce = 0; ce < 2; ce++) {
                        float sim   = acc[mt][nt][rs * 2 + ce];
                        int j = colBase0 + warpCol * 32 + nt * 8 + (lane & 3) * 2 + ce;
                        float logit = 10.0f * sim;
                        float e, arg = fmaf(logit, LOG2E, -10.0f * LOG2E);
                        asm("ex2.approx.ftz.f32 %0, %1;" : "=f"(e) : "f"(arg));
                        float4 B = pb[nt * 2 + ce];
                        bool self = (gi == j);
                        float dot = A.x * B.x + A.y * B.y + A.z * B.z;
                        float d2  = A.w + B.w - 2.0f * dot;
                        bool ispos = (d2 < EPS2) && !self;
                        float ev = self ? 0.0f : e;
                        float pv = ispos ? logit : 0.0f;
                        float cv = ispos ? 1.0f : 0.0f;
                        rse[idx] += ev; rsp[idx] += pv; rct[idx] += cv;
                        int cidx = nt * 2 + ce;
                        cse[cidx] += ev; csp[cidx] += pv; cct[cidx] += cv;
                    }
                }
            }
        }

        // row reduce: 4 lanes (lane&3) share each row
        #pragma unroll
        for (int idx = 0; idx < 8; idx++) {
            float a = rse[idx], b = rsp[idx], c = rct[idx];
            a += __shfl_down_sync(0xffffffffu, a, 2, 4);
            b += __shfl_down_sync(0xffffffffu, b, 2, 4);
            c += __shfl_down_sync(0xffffffffu, c, 2, 4);
            a += __shfl_down_sync(0xffffffffu, a, 1, 4);
            b += __shfl_down_sync(0xffffffffu, b, 1, 4);
            c += __shfl_down_sync(0xffffffffu, c, 1, 4);
            if ((lane & 3) == 0) {
                int rl = (idx >> 1) * 16 + (lane >> 2) + (idx & 1) * 8;
                rbuf_se[wid * 64 + rl] = a;
                rbuf_sp[wid * 64 + rl] = b;
                rbuf_ct[wid * 64 + rl] = c;
            }
        }
        // col reduce: 8 lanes (lane>>2) share each column
        #pragma unroll
        for (int cidx = 0; cidx < 8; cidx++) {
            float a = cse[cidx], b = csp[cidx], c = cct[cidx];
            #pragma unroll
            for (int o = 16; o >= 4; o >>= 1) {
                a += __shfl_down_sync(0xffffffffu, a, o);
                b += __shfl_down_sync(0xffffffffu, b, o);
                c += __shfl_down_sync(0xffffffffu, c, o);
            }
            if (lane < 4) {
                int cl = (cidx >> 1) * 8 + lane * 2 + (cidx & 1);
                cbuf_se[wid * 32 + cl] = a;
                cbuf_sp[wid * 32 + cl] = b;
                cbuf_ct[wid * 32 + cl] = c;
            }
        }
        __syncthreads();

        // combine across warps, write deterministic per-pair slots
        const int slot = p * 128;
        if (tid < 128) {
            int half = tid >> 6, loc = tid & 63;
            float a = 0.f, b = 0.f, c = 0.f;
            #pragma unroll
            for (int wc = 0; wc < 4; wc++) {
                int w = half * 4 + wc;
                a += rbuf_se[w * 64 + loc];
                b += rbuf_sp[w * 64 + loc];
                c += rbuf_ct[w * 64 + loc];
            }
            g_dse[slot + tid] = a; g_dsp[slot + tid] = b; g_dct[slot + tid] = c;
        } else if (!diag) {
            int tcl = tid - 128, wc = tcl >> 5, c5 = tcl & 31;
            float a = cbuf_se[wc * 32 + c5] + cbuf_se[(4 + wc) * 32 + c5];
            float b = cbuf_sp[wc * 32 + c5] + cbuf_sp[(4 + wc) * 32 + c5];
            float c = cbuf_ct[wc * 32 + c5] + cbuf_ct[(4 + wc) * 32 + c5];
            g_tse[slot + tcl] = a; g_tsp[slot + tcl] = b; g_tct[slot + tcl] = c;
        }

        I = nI; J = nJ; buf ^= 1;
    }
}

// ---------------- final reduction over triangle slots ----------------
__device__ __forceinline__ int tri_base(int I) { return I * NBLK - (I * (I - 1)) / 2; }

// grid 64 (one per anchor tile-row R), block 1024: tid = (slotGroup<<7) | anchorLocal
__global__ void final_partial_kernel() {
    __shared__ float s_se[8][128], s_sp[8][128], s_ct[8][128];
    __shared__ float sL[4], sV[4];
    const int tid = threadIdx.x;
    const int rr = tid & 127, sg = tid >> 7;
    const int R = blockIdx.x;
    const int nd = NBLK - R;
    float se = 0.f, sp = 0.f, c = 0.f;
    #pragma unroll
    for (int k = 0; k < 8; k++) {
        int s = sg * 8 + k;
        int id; const float *pse, *psp, *pct;
        if (s < nd) { id = tri_base(R) + s;            pse = g_dse; psp = g_dsp; pct = g_dct; }
        else        { int I = s - nd;
                      id = tri_base(I) + (R - I);      pse = g_tse; psp = g_tsp; pct = g_tct; }
        se += pse[id * 128 + rr]; sp += psp[id * 128 + rr]; c += pct[id * 128 + rr];
    }
    s_se[sg][rr] = se; s_sp[sg][rr] = sp; s_ct[sg][rr] = c;
    __syncthreads();
    if (tid < 128) {
        float a = 0.f, b = 0.f, cc = 0.f;
        #pragma unroll
        for (int g = 0; g < 8; g++) { a += s_se[g][tid]; b += s_sp[g][tid]; cc += s_ct[g][tid]; }
        float lse = logf(a) + 10.0f;
        float L = 0.f, V = 0.f;
        if (cc > 0.0f) { L = -(b - cc * lse) / cc; V = 1.0f; }
        #pragma unroll
        for (int o = 16; o; o >>= 1) {
            L += __shfl_down_sync(0xffffffffu, L, o);
            V += __shfl_down_sync(0xffffffffu, V, o);
        }
        if ((tid & 31) == 0) { sL[tid >> 5] = L; sV[tid >> 5] = V; }
    }
    __syncthreads();
    if (tid == 0) {
        g_partL[blockIdx.x] = sL[0] + sL[1] + sL[2] + sL[3];
        g_partV[blockIdx.x] = sV[0] + sV[1] + sV[2] + sV[3];
    }
}

__global__ void final_combine_kernel(float* __restrict__ out) {
    int tid = threadIdx.x;   // 32 threads
    float a = g_partL[tid] + g_partL[tid + 32];
    float b = g_partV[tid] + g_partV[tid + 32];
    #pragma unroll
    for (int o = 16; o; o >>= 1) {
        a += __shfl_down_sync(0xffffffffu, a, o);
        b += __shfl_down_sync(0xffffffffu, b, o);
    }
    if (tid == 0) out[0] = a / fmaxf(b, 1.0f);
}

// ---------------- launch ----------------
extern "C" void kernel_launch(void* const* d_in, const int* in_sizes, int n_in,
                              void* d_out, int out_size) {
    const float* h   = (const float*)d_in[0];
    const float* pos = (const float*)d_in[1];
    if (n_in >= 2 && in_sizes[0] < in_sizes[1]) {
        const float* t = h; h = pos; pos = t;
    }
    float* out = (float*)d_out;

    prep_kernel<<<N / 8, 256>>>(h);
    pos_kernel<<<N / 256, 256>>>(pos);

    cudaFuncSetAttribute(main_kernel, cudaFuncAttributeMaxDynamicSharedMemorySize, SMEM_REQ);
    main_kernel<<<NCTAS, 256, SMEM_REQ>>>();

    final_partial_kernel<<<64, 1024>>>();
    final_combine_kernel<<<1, 32>>>(out);
}

// round 9
// speedup vs baseline: 16.9650x; 1.7380x over previous
#include <cuda_runtime.h>
#include <cuda_fp16.h>
#include <cstdint>

#define N 8192
#define D 128
#define NBLK 64               // 64 tiles of 128 rows/cols
#define TILEB 32768           // one 128x128 fp16 tile, bytes
#define NCTA 2080             // upper-triangle tile pairs (64*65/2)
#define NCTAS 304             // persistent CTAs: 2 per SM on 152 SMs
#define EPS2 0.25f
#define LOG2E 1.4426950408889634f

// ---------------- device scratch ----------------
__device__ uint4  g_hf[NBLK * 2048];   // fp16 tiles, ldmatrix-swizzled
__device__ float4 g_pos4[N];           // (x,y,z,|p|^2)
__device__ float  g_dse[NCTA * 128], g_dsp[NCTA * 128], g_dct[NCTA * 128];  // row (block I) partials
__device__ float  g_tse[NCTA * 128], g_tsp[NCTA * 128], g_tct[NCTA * 128];  // col (block J) partials
__device__ float  g_partL[64], g_partV[64];

// ---------------- portable PTX helpers ----------------
#define CP16(dst, src) \
    asm volatile("cp.async.cg.shared.global [%0], [%1], 16;\n" :: "r"(dst), "l"(src) : "memory")
#define CP_COMMIT() asm volatile("cp.async.commit_group;\n" ::: "memory")
#define CP_WAIT0()  asm volatile("cp.async.wait_group 0;\n" ::: "memory")

#define LDSM4(r0, r1, r2, r3, addr) \
    asm volatile("ldmatrix.sync.aligned.m8n8.x4.shared.b16 {%0,%1,%2,%3}, [%4];" \
                 : "=r"(r0), "=r"(r1), "=r"(r2), "=r"(r3) : "r"(addr))

#define MMA16816(d, a, b0, b1) \
    asm volatile("mma.sync.aligned.m16n8k16.row.col.f32.f16.f16.f32 " \
                 "{%0,%1,%2,%3}, {%4,%5,%6,%7}, {%8,%9}, {%0,%1,%2,%3};" \
                 : "+f"((d)[0]), "+f"((d)[1]), "+f"((d)[2]), "+f"((d)[3]) \
                 : "r"((a)[0]), "r"((a)[1]), "r"((a)[2]), "r"((a)[3]), "r"(b0), "r"(b1))

__device__ __host__ __forceinline__ uint32_t swz(uint32_t x, uint32_t c16) {
    return (c16 & 8u) | ((c16 & 7u) ^ x);
}

// ---------------- prep: normalize + fp16 convert + swizzled tile store ----------------
__global__ void prep_kernel(const float* __restrict__ h) {
    int row  = blockIdx.x * 8 + (threadIdx.x >> 5);
    int lane = threadIdx.x & 31;
    float4 v = ((const float4*)h)[row * 32 + lane];
    float ss = v.x * v.x + v.y * v.y + v.z * v.z + v.w * v.w;
    #pragma unroll
    for (int o = 16; o; o >>= 1) ss += __shfl_xor_sync(0xffffffffu, ss, o);
    float inv = 1.0f / fmaxf(sqrtf(ss), 1e-12f);
    float x[4] = {v.x * inv, v.y * inv, v.z * inv, v.w * inv};
    unsigned short hb[4];
    #pragma unroll
    for (int j = 0; j < 4; j++) hb[j] = __half_as_ushort(__float2half_rn(x[j]));
    uint2 hu = make_uint2((uint32_t)hb[0] | ((uint32_t)hb[1] << 16),
                          (uint32_t)hb[2] | ((uint32_t)hb[3] << 16));
    int blk = row >> 7, r = row & 127;
    uint32_t c16 = (uint32_t)(lane >> 1);
    uint32_t soff = (uint32_t)r * 256u + swz((uint32_t)(r & 7), c16) * 16u
                    + (uint32_t)(lane & 1) * 8u;
    *(uint2*)((char*)g_hf + (size_t)blk * TILEB + soff) = hu;
}

__global__ void pos_kernel(const float* __restrict__ pos) {
    int i = blockIdx.x * blockDim.x + threadIdx.x;
    if (i < N) {
        float x = pos[3 * i], y = pos[3 * i + 1], z = pos[3 * i + 2];
        g_pos4[i] = make_float4(x, y, z, x * x + y * y + z * z);
    }
}

// ---------------- main kernel: persistent, pipelined tile pairs, occ 2 ----------------
// smem: A 0..32K | B buf0 32K..64K | B buf1 64K..96K | red @96K (9216 B)
#define ASM 0
#define BBUF(b) (32768 + (b) * 32768)
#define RED 98304
#define SMEM_REQ (RED + 9216)   // 107520

__device__ __forceinline__ void load_tile16(uint32_t dst, int blk, int tid) {
    const char* gh = (const char*)g_hf + (size_t)blk * TILEB;
    #pragma unroll
    for (int i = 0; i < 8; i++) {
        uint32_t o = (uint32_t)(tid * 128 + i * 16);
        CP16(dst + o, gh + o);
    }
}

__global__ void __launch_bounds__(256, 2) main_kernel() {
    extern __shared__ __align__(128) char smem[];
    const uint32_t sbase = (uint32_t)__cvta_generic_to_shared(smem);
    float* rbuf_se = (float*)(smem + RED);
    float* rbuf_sp = rbuf_se + 512;
    float* rbuf_ct = rbuf_sp + 512;
    float* cbuf_se = rbuf_ct + 512;
    float* cbuf_sp = cbuf_se + 256;
    float* cbuf_ct = cbuf_sp + 256;

    const int tid = threadIdx.x, wid = tid >> 5, lane = tid & 31;
    const int warpRow = wid >> 2, warpCol = wid & 3;

    // pair range for this persistent CTA
    const int p0 = (int)((long long)blockIdx.x * NCTA / NCTAS);
    const int p1 = (int)((long long)(blockIdx.x + 1) * NCTA / NCTAS);
    if (p0 >= p1) return;

    // decode p0 -> (I, J)
    int I = 0, t = p0;
    while (t >= NBLK - I) { t -= NBLK - I; I++; }
    int J = I + t;

    // ---- fragment address constants ----
    uint32_t aAddr[4], axr[4];
    #pragma unroll
    for (int mt = 0; mt < 4; mt++) {
        uint32_t r = (uint32_t)(warpRow * 64 + mt * 16 + (lane & 15));
        aAddr[mt] = sbase + ASM + r * 256u;
        axr[mt]   = r & 7u;
    }
    const uint32_t aSel = (uint32_t)((lane >> 4) & 1);
    uint32_t bOff[2], bxr[2];
    #pragma unroll
    for (int ntp = 0; ntp < 2; ntp++) {
        uint32_t n = (uint32_t)(warpCol * 32 + ntp * 16 + ((lane >> 4) & 1) * 8 + (lane & 7));
        bOff[ntp] = n * 256u;
        bxr[ntp]  = n & 7u;
    }
    const uint32_t bSel = (uint32_t)((lane >> 3) & 1);

    // ---- prologue: A(I) + B(J) into buf 0 ----
    load_tile16(sbase + ASM, I, tid);
    load_tile16(sbase + BBUF(0), J, tid);
    CP_COMMIT();

    int buf = 0;
    for (int p = p0; p < p1; p++) {
        int nI = I, nJ = J + 1;
        if (nJ == NBLK) { nI = I + 1; nJ = nI; }
        const bool havenext = (p + 1 < p1);
        const bool nextSame = havenext && (nI == I);

        CP_WAIT0();
        __syncthreads();

        // prefetch next B now if A stays resident (overlaps the GEMM)
        if (nextSame) {
            load_tile16(sbase + BBUF(buf ^ 1), nJ, tid);
            CP_COMMIT();
        }

        const uint32_t baseB = sbase + BBUF(buf);

        float acc[4][4][4];
        #pragma unroll
        for (int mt = 0; mt < 4; mt++)
            #pragma unroll
            for (int nt = 0; nt < 4; nt++)
                #pragma unroll
                for (int c = 0; c < 4; c++) acc[mt][nt][c] = 0.f;

        // ---- single-pass fp16 GEMM ----
        #pragma unroll 2
        for (int step = 0; step < 8; step++) {
            const uint32_t c16a = (uint32_t)(2 * step) + aSel;
            const uint32_t c16b = (uint32_t)(2 * step) + bSel;
            uint32_t bh[2][4], af[4][4];
            #pragma unroll
            for (int ntp = 0; ntp < 2; ntp++) {
                uint32_t sw = swz(bxr[ntp], c16b) << 4;
                LDSM4(bh[ntp][0], bh[ntp][1], bh[ntp][2], bh[ntp][3], baseB + bOff[ntp] + sw);
            }
            #pragma unroll
            for (int mt = 0; mt < 4; mt++) {
                uint32_t sw = swz(axr[mt], c16a) << 4;
                LDSM4(af[mt][0], af[mt][1], af[mt][2], af[mt][3], aAddr[mt] + sw);
            }
            #pragma unroll
            for (int mt = 0; mt < 4; mt++)
                #pragma unroll
                for (int nt = 0; nt < 4; nt++)
                    MMA16816(acc[mt][nt], af[mt], bh[nt >> 1][(nt & 1) * 2], bh[nt >> 1][(nt & 1) * 2 + 1]);
        }

        __syncthreads();   // all warps done reading A and B[buf]

        // A-transition: load new A (+ next B), overlapping the epilogue
        if (havenext && !nextSame) {
            load_tile16(sbase + ASM, nI, tid);
            load_tile16(sbase + BBUF(buf ^ 1), nJ, tid);
            CP_COMMIT();
        }

        // ---- epilogue: fold into row (block I) AND column (block J) accumulators ----
        const int rowBase = I * 128, colBase0 = J * 128;
        const bool diag = (I == J);
        float cse[8], csp[8], cct[8];
        #pragma unroll
        for (int i = 0; i < 8; i++) { cse[i] = 0.f; csp[i] = 0.f; cct[i] = 0.f; }
        float4 pb[8];
        #pragma unroll
        for (int nt = 0; nt < 4; nt++)
            #pragma unroll
            for (int ce = 0; ce < 2; ce++)
                pb[nt * 2 + ce] = __ldg(&g_pos4[colBase0 + warpCol * 32 + nt * 8 + (lane & 3) * 2 + ce]);

        #pragma unroll
        for (int mt = 0; mt < 4; mt++) {
            #pragma unroll
            for (int rs = 0; rs < 2; rs++) {
                const int gi = rowBase + warpRow * 64 + mt * 16 + (lane >> 2) + rs * 8;
                const float4 A = __ldg(&g_pos4[gi]);
                float a_se = 0.f, a_sp = 0.f, a_ct = 0.f;     // transient row sums
                #pragma unroll
                for (int nt = 0; nt < 4; nt++) {
                    #pragma unroll
                    for (int ce = 0; ce < 2; ce++) {
                        float sim   = acc[mt][nt][rs * 2 + ce];
                        int j = colBase0 + warpCol * 32 + nt * 8 + (lane & 3) * 2 + ce;
                        float logit = 10.0f * sim;
                        float e, arg = fmaf(logit, LOG2E, -10.0f * LOG2E);
                        asm("ex2.approx.ftz.f32 %0, %1;" : "=f"(e) : "f"(arg));
                        float4 B = pb[nt * 2 + ce];
                        bool self = (gi == j);
                        float dot = A.x * B.x + A.y * B.y + A.z * B.z;
                        float d2  = A.w + B.w - 2.0f * dot;
                        bool ispos = (d2 < EPS2) && !self;
                        float ev = self ? 0.0f : e;
                        float pv = ispos ? logit : 0.0f;
                        float cv = ispos ? 1.0f : 0.0f;
                        a_se += ev; a_sp += pv; a_ct += cv;
                        int cidx = nt * 2 + ce;
                        cse[cidx] += ev; csp[cidx] += pv; cct[cidx] += cv;
                    }
                }
                // immediate row reduce over the 4 lanes (lane&3) sharing this row
                a_se += __shfl_down_sync(0xffffffffu, a_se, 2, 4);
                a_sp += __shfl_down_sync(0xffffffffu, a_sp, 2, 4);
                a_ct += __shfl_down_sync(0xffffffffu, a_ct, 2, 4);
                a_se += __shfl_down_sync(0xffffffffu, a_se, 1, 4);
                a_sp += __shfl_down_sync(0xffffffffu, a_sp, 1, 4);
                a_ct += __shfl_down_sync(0xffffffffu, a_ct, 1, 4);
                if ((lane & 3) == 0) {
                    int rl = mt * 16 + rs * 8 + (lane >> 2);
                    rbuf_se[wid * 64 + rl] = a_se;
                    rbuf_sp[wid * 64 + rl] = a_sp;
                    rbuf_ct[wid * 64 + rl] = a_ct;
                }
            }
        }

        // col reduce: 8 lanes (lane>>2) share each column
        #pragma unroll
        for (int cidx = 0; cidx < 8; cidx++) {
            float a = cse[cidx], b = csp[cidx], c = cct[cidx];
            #pragma unroll
            for (int o = 16; o >= 4; o >>= 1) {
                a += __shfl_down_sync(0xffffffffu, a, o);
                b += __shfl_down_sync(0xffffffffu, b, o);
                c += __shfl_down_sync(0xffffffffu, c, o);
            }
            if (lane < 4) {
                int cl = (cidx >> 1) * 8 + lane * 2 + (cidx & 1);
                cbuf_se[wid * 32 + cl] = a;
                cbuf_sp[wid * 32 + cl] = b;
                cbuf_ct[wid * 32 + cl] = c;
            }
        }
        __syncthreads();

        // combine across warps, write deterministic per-pair slots
        const int slot = p * 128;
        if (tid < 128) {
            int half = tid >> 6, loc = tid & 63;
            float a = 0.f, b = 0.f, c = 0.f;
            #pragma unroll
            for (int wc = 0; wc < 4; wc++) {
                int w = half * 4 + wc;
                a += rbuf_se[w * 64 + loc];
                b += rbuf_sp[w * 64 + loc];
                c += rbuf_ct[w * 64 + loc];
            }
            g_dse[slot + tid] = a; g_dsp[slot + tid] = b; g_dct[slot + tid] = c;
        } else if (!diag) {
            int tcl = tid - 128, wc = tcl >> 5, c5 = tcl & 31;
            float a = cbuf_se[wc * 32 + c5] + cbuf_se[(4 + wc) * 32 + c5];
            float b = cbuf_sp[wc * 32 + c5] + cbuf_sp[(4 + wc) * 32 + c5];
            float c = cbuf_ct[wc * 32 + c5] + cbuf_ct[(4 + wc) * 32 + c5];
            g_tse[slot + tcl] = a; g_tsp[slot + tcl] = b; g_tct[slot + tcl] = c;
        }

        I = nI; J = nJ; buf ^= 1;
    }
}

// ---------------- final reduction over triangle slots ----------------
__device__ __forceinline__ int tri_base(int I) { return I * NBLK - (I * (I - 1)) / 2; }

// grid 64 (one per anchor tile-row R), block 1024: tid = (slotGroup<<7) | anchorLocal
__global__ void final_partial_kernel() {
    __shared__ float s_se[8][128], s_sp[8][128], s_ct[8][128];
    __shared__ float sL[4], sV[4];
    const int tid = threadIdx.x;
    const int rr = tid & 127, sg = tid >> 7;
    const int R = blockIdx.x;
    const int nd = NBLK - R;
    float se = 0.f, sp = 0.f, c = 0.f;
    #pragma unroll
    for (int k = 0; k < 8; k++) {
        int s = sg * 8 + k;
        int id; const float *pse, *psp, *pct;
        if (s < nd) { id = tri_base(R) + s;            pse = g_dse; psp = g_dsp; pct = g_dct; }
        else        { int I = s - nd;
                      id = tri_base(I) + (R - I);      pse = g_tse; psp = g_tsp; pct = g_tct; }
        se += pse[id * 128 + rr]; sp += psp[id * 128 + rr]; c += pct[id * 128 + rr];
    }
    s_se[sg][rr] = se; s_sp[sg][rr] = sp; s_ct[sg][rr] = c;
    __syncthreads();
    if (tid < 128) {
        float a = 0.f, b = 0.f, cc = 0.f;
        #pragma unroll
        for (int g = 0; g < 8; g++) { a += s_se[g][tid]; b += s_sp[g][tid]; cc += s_ct[g][tid]; }
        float lse = logf(a) + 10.0f;
        float L = 0.f, V = 0.f;
        if (cc > 0.0f) { L = -(b - cc * lse) / cc; V = 1.0f; }
        #pragma unroll
        for (int o = 16; o; o >>= 1) {
            L += __shfl_down_sync(0xffffffffu, L, o);
            V += __shfl_down_sync(0xffffffffu, V, o);
        }
        if ((tid & 31) == 0) { sL[tid >> 5] = L; sV[tid >> 5] = V; }
    }
    __syncthreads();
    if (tid == 0) {
        g_partL[blockIdx.x] = sL[0] + sL[1] + sL[2] + sL[3];
        g_partV[blockIdx.x] = sV[0] + sV[1] + sV[2] + sV[3];
    }
}

__global__ void final_combine_kernel(float* __restrict__ out) {
    int tid = threadIdx.x;   // 32 threads
    float a = g_partL[tid] + g_partL[tid + 32];
    float b = g_partV[tid] + g_partV[tid + 32];
    #pragma unroll
    for (int o = 16; o; o >>= 1) {
        a += __shfl_down_sync(0xffffffffu, a, o);
        b += __shfl_down_sync(0xffffffffu, b, o);
    }
    if (tid == 0) out[0] = a / fmaxf(b, 1.0f);
}

// ---------------- launch ----------------
extern "C" void kernel_launch(void* const* d_in, const int* in_sizes, int n_in,
                              void* d_out, int out_size) {
    const float* h   = (const float*)d_in[0];
    const float* pos = (const float*)d_in[1];
    if (n_in >= 2 && in_sizes[0] < in_sizes[1]) {
        const float* t = h; h = pos; pos = t;
    }
    float* out = (float*)d_out;

    prep_kernel<<<N / 8, 256>>>(h);
    pos_kernel<<<N / 256, 256>>>(pos);

    cudaFuncSetAttribute(main_kernel, cudaFuncAttributeMaxDynamicSharedMemorySize, SMEM_REQ);
    main_kernel<<<NCTAS, 256, SMEM_REQ>>>();

    final_partial_kernel<<<64, 1024>>>();
    final_combine_kernel<<<1, 32>>>(out);
}